// round 7
// baseline (speedup 1.0000x reference)
#include <cuda_runtime.h>
#include <cuda_fp16.h>
#include <cstdint>

#define HW 4096
#define DDIM 64
#define NSLICE 256          // total K slices of 16
#define QSLICE 64           // slices per K-quarter (per warp)

// B fragments, lane-major: g_fp[gs][q][lane][4 x b32]; uint4 index = gs*128 + q*32 + lane
// K-permutation (matches float4 A loads): real k = (l&3)*4 + pair*2
__device__ uint32_t g_fp[NSLICE * 4 * 32 * 4];

// ---------------------------------------------------------------------------
// Kernel 1: build packed B fragments of f[m,d] = cos(8pi*(w0*gx + w1*gy + b))
// ---------------------------------------------------------------------------
__global__ void pos_enc_kernel(const float* __restrict__ w,
                               const float* __restrict__ bias) {
    int idx = blockIdx.x * blockDim.x + threadIdx.x;
    if (idx >= NSLICE * 512) return;
    int c    = idx & 3;
    int l    = (idx >> 2) & 31;
    int q    = (idx >> 7) & 3;
    int gs   = idx >> 9;
    int j    = q * 2 + (c >> 1);
    int pair = c & 1;
    int d    = j * 8 + (l >> 2);
    int k    = (l & 3) * 4 + pair * 2;
    int m0   = gs * 16 + k;
    float w0 = w[2 * d], w1 = w[2 * d + 1], bd = bias[d];
    float v[2];
#pragma unroll
    for (int t = 0; t < 2; t++) {
        int m = m0 + t;
        int x = m & 63, y = m >> 6;
        float gx = (float)(2 * x - 63) * (1.0f / 64.0f);
        float gy = (float)(2 * y - 63) * (1.0f / 64.0f);
        v[t] = cosf(25.132741228718345f * fmaf(w0, gx, fmaf(w1, gy, bd)));
    }
    __half2 h = __floats2half2_rn(v[0], v[1]);
    g_fp[idx] = *reinterpret_cast<uint32_t*>(&h);
}

// ---------------------------------------------------------------------------
static __device__ __forceinline__ uint32_t e2p(float a, float b) {
    __half2 h = __floats2half2_rn(__expf(a), __expf(b));
    return *reinterpret_cast<uint32_t*>(&h);
}

#define MMA(dst, a0, a1, a2, a3, b0, b1)                                        \
    asm volatile("mma.sync.aligned.m16n8k16.row.col.f32.f16.f16.f32 "           \
                 "{%0,%1,%2,%3},{%4,%5,%6,%7},{%8,%9},{%0,%1,%2,%3};"           \
                 : "+f"(dst[0]), "+f"(dst[1]), "+f"(dst[2]), "+f"(dst[3])       \
                 : "r"(a0), "r"(a1), "r"(a2), "r"(a3), "r"(b0), "r"(b1))

// issue A copy for slice s into ring slot j (warp-private; thread copies its own 16B x2)
#define CPA(j, s)                                                               \
    do { const float* _g = pA + (size_t)(s) * 16;                               \
        uint32_t _d = ringw + (j) * 1024 + l * 16;                              \
        asm volatile("cp.async.cg.shared.global [%0], [%1], 16;"                \
                     :: "r"(_d), "l"(_g) : "memory");                           \
        asm volatile("cp.async.cg.shared.global [%0], [%1], 16;"                \
                     :: "r"(_d + 512), "l"(_g + 8 * HW) : "memory");            \
        asm volatile("cp.async.commit_group;" ::: "memory");                    \
    } while (0)

#define STAGE(j, sidx)                                                          \
    do {                                                                        \
        if ((sidx) + 3 < QSLICE) { CPA(((sidx) + 3) & 3, (sidx) + 3); }         \
        else asm volatile("cp.async.commit_group;" ::: "memory");               \
        asm volatile("cp.async.wait_group 3;" ::: "memory");                    \
        const uint4* _bp = pB + (size_t)(sidx) * 128;                           \
        uint4 B0 = __ldg(_bp);      uint4 B1 = __ldg(_bp + 32);                 \
        uint4 B2 = __ldg(_bp + 64); uint4 B3 = __ldg(_bp + 96);                 \
        float4 A0 = *(const float4*)(smRing + (j) * 1024 + l * 16);             \
        float4 A1 = *(const float4*)(smRing + (j) * 1024 + 512 + l * 16);       \
        uint32_t ra0 = e2p(A0.x, A0.y);                                         \
        uint32_t ra2 = e2p(A0.z, A0.w);                                         \
        uint32_t ra1 = e2p(A1.x, A1.y);                                         \
        uint32_t ra3 = e2p(A1.z, A1.w);                                         \
        MMA(acc[0], ra0, ra1, ra2, ra3, B0.x, B0.y);                            \
        MMA(acc[1], ra0, ra1, ra2, ra3, B0.z, B0.w);                            \
        MMA(acc[2], ra0, ra1, ra2, ra3, B1.x, B1.y);                            \
        MMA(acc[3], ra0, ra1, ra2, ra3, B1.z, B1.w);                            \
        MMA(acc[4], ra0, ra1, ra2, ra3, B2.x, B2.y);                            \
        MMA(acc[5], ra0, ra1, ra2, ra3, B2.z, B2.w);                            \
        MMA(acc[6], ra0, ra1, ra2, ra3, B3.x, B3.y);                            \
        MMA(acc[7], ra0, ra1, ra2, ra3, B3.z, B3.w);                            \
        MMA(acc[8], ra0, ra1, ra2, ra3, bz, bz);                                \
    } while (0)

struct SmemT {
    union {
        float4 ring[4 * 4 * 64];     // 4 warps x 4 slots x 1KB = 16 KB
        float  Cp[4][16][68];        // K-quarter partials, 17408 B
    } u;
    float Zp[4][16];
    float Zr[16];
};

// ---------------------------------------------------------------------------
// Kernel 2: 128-thr CTA = 4 warps = 4 K-quarters over one 16-row tile.
// cp.async warp-private A ring (depth 4) -> smem -> exp -> 9 MMAs.
// Grid 1024 CTAs for balance + high occupancy.
// ---------------------------------------------------------------------------
__global__ __launch_bounds__(128, 5)
void gp_kernel(const float* __restrict__ sim, float* __restrict__ out) {
    __shared__ SmemT sm;

    const int tid = threadIdx.x;
    const int l   = tid & 31;
    const int w   = tid >> 5;          // K-quarter
    const int bb  = blockIdx.y;
    const int row0 = blockIdx.x * 16;

    const float* pA = sim + ((size_t)bb * HW + row0 + (l >> 2)) * (size_t)HW
                          + w * (QSLICE * 16) + (l & 3) * 4;
    const uint4* pB = ((const uint4*)g_fp) + (size_t)w * QSLICE * 128 + l;

    uint32_t ring_base;
    asm("{ .reg .u64 t; cvta.to.shared.u64 t, %1; cvt.u32.u64 %0, t; }"
        : "=r"(ring_base) : "l"((void*)&sm.u.ring[0]));
    const uint32_t ringw = ring_base + w * 4096;
    const char* smRing = (const char*)&sm.u.ring[0] + w * 4096;

    float acc[9][4];
#pragma unroll
    for (int i = 0; i < 9; i++)
#pragma unroll
        for (int k = 0; k < 4; k++) acc[i][k] = 0.0f;

    const uint32_t bz = (l < 4) ? 0x3C003C00u : 0u;  // ones in B col n=0

    CPA(0, 0); CPA(1, 1); CPA(2, 2);

#pragma unroll 1
    for (int s = 0; s < QSLICE; s += 4) {
        STAGE(0, s);
        STAGE(1, s + 1);
        STAGE(2, s + 2);
        STAGE(3, s + 3);
    }

    // ---- epilogue: merge 4 K-quarter partials, divide by Z, store ----
    __syncthreads();   // ring reads done in all warps before union reuse
    const int lr = l >> 2;
#pragma unroll
    for (int j = 0; j < 8; j++) {
        const int c0 = j * 8 + (l & 3) * 2;
        *(float2*)&sm.u.Cp[w][lr][c0]     = make_float2(acc[j][0], acc[j][1]);
        *(float2*)&sm.u.Cp[w][lr + 8][c0] = make_float2(acc[j][2], acc[j][3]);
    }
    if ((l & 3) == 0) { sm.Zp[w][lr] = acc[8][0]; sm.Zp[w][lr + 8] = acc[8][2]; }
    __syncthreads();

    if (tid < 16)
        sm.Zr[tid] = 1.0f / (sm.Zp[0][tid] + sm.Zp[1][tid] +
                             sm.Zp[2][tid] + sm.Zp[3][tid]);
    __syncthreads();

    {
        const int d = tid >> 1, nh = tid & 1;
        float* go = out + ((size_t)(bb * DDIM + d)) * HW + row0 + nh * 8;
#pragma unroll
        for (int i = 0; i < 2; i++) {
            float4 o;
#pragma unroll
            for (int k = 0; k < 4; k++) {
                const int n = nh * 8 + i * 4 + k;
                float v = sm.u.Cp[0][n][d] + sm.u.Cp[1][n][d] +
                          sm.u.Cp[2][n][d] + sm.u.Cp[3][n][d];
                (&o.x)[k] = v * sm.Zr[n];
            }
            *(float4*)(go + i * 4) = o;
        }
    }
}

// ---------------------------------------------------------------------------
extern "C" void kernel_launch(void* const* d_in, const int* in_sizes, int n_in,
                              void* d_out, int out_size) {
    const float* sim  = (const float*)d_in[0];  // [4, 4096, 4096] fp32
    const float* w    = (const float*)d_in[1];  // [64, 2] fp32
    const float* bias = (const float*)d_in[2];  // [64] fp32
    float* out = (float*)d_out;                 // [4, 64, 64, 64] fp32

    pos_enc_kernel<<<(NSLICE * 512 + 255) / 256, 256>>>(w, bias);

    dim3 grid(HW / 16, 4);
    gp_kernel<<<grid, 128>>>(sim, out);
}

// round 8
// speedup vs baseline: 1.0752x; 1.0752x over previous
#include <cuda_runtime.h>
#include <cuda_fp16.h>
#include <cstdint>

#define HW 4096
#define DDIM 64
#define NSLICE 256          // total K slices of 16
#define HSLICE 128          // slices per K-half
#define CS_STRIDE 66

// B fragments, lane-major: g_fp[gs][q][lane][4 x b32]; uint4 index = gs*128 + q*32 + lane
// K-permutation (matches float4 A loads): real k = (l&3)*4 + pair*2
__device__ uint32_t g_fp[NSLICE * 4 * 32 * 4];

// ---------------------------------------------------------------------------
// Kernel 1: build packed B fragments of f[m,d] = cos(8pi*(w0*gx + w1*gy + b))
// ---------------------------------------------------------------------------
__global__ void pos_enc_kernel(const float* __restrict__ w,
                               const float* __restrict__ bias) {
    int idx = blockIdx.x * blockDim.x + threadIdx.x;
    if (idx >= NSLICE * 512) return;
    int c    = idx & 3;
    int l    = (idx >> 2) & 31;
    int q    = (idx >> 7) & 3;
    int gs   = idx >> 9;
    int j    = q * 2 + (c >> 1);
    int pair = c & 1;
    int d    = j * 8 + (l >> 2);
    int k    = (l & 3) * 4 + pair * 2;
    int m0   = gs * 16 + k;
    float w0 = w[2 * d], w1 = w[2 * d + 1], bd = bias[d];
    float v[2];
#pragma unroll
    for (int t = 0; t < 2; t++) {
        int m = m0 + t;
        int x = m & 63, y = m >> 6;
        float gx = (float)(2 * x - 63) * (1.0f / 64.0f);
        float gy = (float)(2 * y - 63) * (1.0f / 64.0f);
        v[t] = cosf(25.132741228718345f * fmaf(w0, gx, fmaf(w1, gy, bd)));
    }
    __half2 h = __floats2half2_rn(v[0], v[1]);
    g_fp[idx] = *reinterpret_cast<uint32_t*>(&h);
}

// ---------------------------------------------------------------------------
#define MMA(dst, a0, a1, a2, a3, b0, b1)                                        \
    asm volatile("mma.sync.aligned.m16n8k16.row.col.f32.f16.f16.f32 "           \
                 "{%0,%1,%2,%3},{%4,%5,%6,%7},{%8,%9},{%0,%1,%2,%3};"           \
                 : "+f"(dst[0]), "+f"(dst[1]), "+f"(dst[2]), "+f"(dst[3])       \
                 : "r"(a0), "r"(a1), "r"(a2), "r"(a3), "r"(b0), "r"(b1))

#define LA(st, s)                                                               \
    do { const float* _p = pA + (size_t)(s) * 16;                               \
        R[st][0] = __ldcs((const float4*)_p);                                   \
        R[st][1] = __ldcs((const float4*)(_p + 8 * HW)); } while (0)

#define LB(st, s)                                                               \
    do { const uint4* _p = pB + (size_t)(s) * 128;                              \
        Bv[st][0] = __ldg(_p);      Bv[st][1] = __ldg(_p + 32);                 \
        Bv[st][2] = __ldg(_p + 64); Bv[st][3] = __ldg(_p + 96); } while (0)

// exp raw buffer st -> packed P[st]; accumulate Z partials (fma pipe)
#define EXP(st)                                                                 \
    do {                                                                        \
        float e0 = __expf(R[st][0].x), e1 = __expf(R[st][0].y);                 \
        float e2 = __expf(R[st][0].z), e3 = __expf(R[st][0].w);                 \
        z0 += (e0 + e1) + (e2 + e3);                                            \
        __half2 p0 = __floats2half2_rn(e0, e1);                                 \
        __half2 p1 = __floats2half2_rn(e2, e3);                                 \
        P[st][0] = *reinterpret_cast<uint32_t*>(&p0);                           \
        P[st][2] = *reinterpret_cast<uint32_t*>(&p1);                           \
        float e4 = __expf(R[st][1].x), e5 = __expf(R[st][1].y);                 \
        float e6 = __expf(R[st][1].z), e7 = __expf(R[st][1].w);                 \
        z1 += (e4 + e5) + (e6 + e7);                                            \
        __half2 p2 = __floats2half2_rn(e4, e5);                                 \
        __half2 p3 = __floats2half2_rn(e6, e7);                                 \
        P[st][1] = *reinterpret_cast<uint32_t*>(&p2);                           \
        P[st][3] = *reinterpret_cast<uint32_t*>(&p3);                           \
    } while (0)

// Stage s: B for s+1 (dist-1), 8 MMAs on ready P/Bv, exp raw (slice s+2), A load (s+4)
#define STAGE(st, sidx)                                                         \
    do {                                                                        \
        if ((sidx) + 1 < HSLICE) LB((st) ^ 1, (sidx) + 1);                      \
        const uint32_t* bp = (const uint32_t*)Bv[st];                           \
        MMA(acc[0], P[st][0], P[st][1], P[st][2], P[st][3], bp[0],  bp[1]);     \
        MMA(acc[1], P[st][0], P[st][1], P[st][2], P[st][3], bp[2],  bp[3]);     \
        MMA(acc[2], P[st][0], P[st][1], P[st][2], P[st][3], bp[4],  bp[5]);     \
        MMA(acc[3], P[st][0], P[st][1], P[st][2], P[st][3], bp[6],  bp[7]);     \
        MMA(acc[4], P[st][0], P[st][1], P[st][2], P[st][3], bp[8],  bp[9]);     \
        MMA(acc[5], P[st][0], P[st][1], P[st][2], P[st][3], bp[10], bp[11]);    \
        MMA(acc[6], P[st][0], P[st][1], P[st][2], P[st][3], bp[12], bp[13]);    \
        MMA(acc[7], P[st][0], P[st][1], P[st][2], P[st][3], bp[14], bp[15]);    \
        if ((sidx) + 2 < HSLICE) EXP(st);                                       \
        if ((sidx) + 4 < HSLICE) LA(st, (sidx) + 4);                            \
    } while (0)

// ---------------------------------------------------------------------------
// Kernel 2: 8 warps = 4 row-groups x 2 K-halves. Warp: 16 rows x 64 N x K=2048.
// Early-exp A pipeline (issue dist 4, exp dist 2) + B dist-1 ping-pong.
// Z via FADD + quad shuffle. No smem/barriers in mainloop.
// ---------------------------------------------------------------------------
__global__ __launch_bounds__(256, 2)
void gp_kernel(const float* __restrict__ sim, float* __restrict__ out) {
    __shared__ float Cs[64][CS_STRIDE];
    __shared__ float Zs[64];
    __shared__ float Zr[64];

    const int tid = threadIdx.x;
    const int l   = tid & 31;
    const int w   = tid >> 5;
    const int wm  = w & 3;       // row group
    const int kh  = w >> 2;      // K half
    const int bb  = blockIdx.y;
    const int row0 = blockIdx.x * 64;

    const float* pA = sim + ((size_t)bb * HW + row0 + wm * 16 + (l >> 2)) * (size_t)HW
                          + kh * (HSLICE * 16) + (l & 3) * 4;
    const uint4* pB = ((const uint4*)g_fp) + (size_t)kh * HSLICE * 128 + l;

    float acc[8][4];
#pragma unroll
    for (int i = 0; i < 8; i++)
#pragma unroll
        for (int k = 0; k < 4; k++) acc[i][k] = 0.0f;

    float z0 = 0.0f, z1 = 0.0f;

    float4   R[2][2];
    uint32_t P[2][4];
    uint4    Bv[2][4];

    // prologue: fill pipeline (slices 0..3 raw, 0..1 packed, B slice 0)
    LA(0, 0); LA(1, 1); LB(0, 0);
    EXP(0); LA(0, 2);
    EXP(1); LA(1, 3);

#pragma unroll 1
    for (int s = 0; s < HSLICE; s += 2) {
        STAGE(0, s);
        STAGE(1, s + 1);
    }

    // ---- epilogue: merge K-halves via smem, divide by Z, coalesced store ----
    // quad-reduce Z (lanes 4q..4q+3 hold partials of rows lr, lr+8)
    z0 += __shfl_xor_sync(0xFFFFFFFFu, z0, 1);
    z0 += __shfl_xor_sync(0xFFFFFFFFu, z0, 2);
    z1 += __shfl_xor_sync(0xFFFFFFFFu, z1, 1);
    z1 += __shfl_xor_sync(0xFFFFFFFFu, z1, 2);

    const int lr = wm * 16 + (l >> 2);
    if (kh == 0) {
#pragma unroll
        for (int j = 0; j < 8; j++) {
            const int c0 = j * 8 + (l & 3) * 2;
            *(float2*)&Cs[lr][c0]     = make_float2(acc[j][0], acc[j][1]);
            *(float2*)&Cs[lr + 8][c0] = make_float2(acc[j][2], acc[j][3]);
        }
        if ((l & 3) == 0) { Zs[lr] = z0; Zs[lr + 8] = z1; }
    }
    __syncthreads();
    if (kh == 1) {
#pragma unroll
        for (int j = 0; j < 8; j++) {
            const int c0 = j * 8 + (l & 3) * 2;
            Cs[lr][c0]         += acc[j][0];
            Cs[lr][c0 + 1]     += acc[j][1];
            Cs[lr + 8][c0]     += acc[j][2];
            Cs[lr + 8][c0 + 1] += acc[j][3];
        }
        if ((l & 3) == 0) { Zs[lr] += z0; Zs[lr + 8] += z1; }
    }
    __syncthreads();
    if (tid < 64) Zr[tid] = 1.0f / Zs[tid];
    __syncthreads();

    {
        const int d = tid >> 2, seg = tid & 3;
        float* go = out + ((size_t)(bb * DDIM + d)) * HW + row0 + seg * 16;
#pragma unroll
        for (int i = 0; i < 4; i++) {
            const int n = seg * 16 + i * 4;
            float4 o;
            o.x = Cs[n + 0][d] * Zr[n + 0];
            o.y = Cs[n + 1][d] * Zr[n + 1];
            o.z = Cs[n + 2][d] * Zr[n + 2];
            o.w = Cs[n + 3][d] * Zr[n + 3];
            *(float4*)(go + i * 4) = o;
        }
    }
}

// ---------------------------------------------------------------------------
extern "C" void kernel_launch(void* const* d_in, const int* in_sizes, int n_in,
                              void* d_out, int out_size) {
    const float* sim  = (const float*)d_in[0];  // [4, 4096, 4096] fp32
    const float* w    = (const float*)d_in[1];  // [64, 2] fp32
    const float* bias = (const float*)d_in[2];  // [64] fp32
    float* out = (float*)d_out;                 // [4, 64, 64, 64] fp32

    pos_enc_kernel<<<(NSLICE * 512 + 255) / 256, 256>>>(w, bias);

    dim3 grid(HW / 64, 4);
    gp_kernel<<<grid, 256>>>(sim, out);
}